// round 2
// baseline (speedup 1.0000x reference)
#include <cuda_runtime.h>
#include <math.h>

#define BATCH 64
#define NPTS  1024
#define KNNK  16
#define HID   64

// Scratch (no allocations allowed)
__device__ float g_x1[BATCH * NPTS * HID];
__device__ float g_x2[BATCH * NPTS * HID];
__device__ float g_x3[BATCH * NPTS * HID];
__device__ int   g_idx[BATCH * NPTS * KNNK];

__device__ __forceinline__ void gbar(int id, int cnt) {
    asm volatile("bar.sync %0, %1;" :: "r"(id), "r"(cnt) : "memory");
}

// acc[k] += src[k] * w for k in 0..15, src read as 4x float4 (broadcast LDS)
__device__ __forceinline__ void fma16(float acc[16], const float* src, float w) {
    const float4* s4 = reinterpret_cast<const float4*>(src);
    float4 a = s4[0], b = s4[1], c = s4[2], d = s4[3];
    acc[0]  += a.x * w; acc[1]  += a.y * w; acc[2]  += a.z * w; acc[3]  += a.w * w;
    acc[4]  += b.x * w; acc[5]  += b.y * w; acc[6]  += b.z * w; acc[7]  += b.w * w;
    acc[8]  += c.x * w; acc[9]  += c.y * w; acc[10] += c.z * w; acc[11] += c.w * w;
    acc[12] += d.x * w; acc[13] += d.y * w; acc[14] += d.z * w; acc[15] += d.w * w;
}

// ============================================================================
// kNN: per (b, i) find 16 smallest of dist = sq_i + sq_j - 2*dot(x_i, x_j).
// Scan j ascending, strict < insertion => lower index wins ties (= lax.top_k).
// Block: 128 threads, each owns one point i. Tiles of 128 j-rows staged in SMEM.
// ============================================================================
template <int C>
__global__ __launch_bounds__(128, 4) void knn_kernel(const float* __restrict__ x,
                                                     int* __restrict__ idx_out) {
    constexpr int PT = 128;
    __shared__ __align__(16) float xs[PT * C];
    __shared__ float sqs[PT];

    int b   = blockIdx.x / (NPTS / PT);
    int t0  = (blockIdx.x % (NPTS / PT)) * PT;
    int tid = threadIdx.x;
    int i   = t0 + tid;
    const float* xb = x + (size_t)b * NPTS * C;

    float xi[C];
    float sqi = 0.f;
    if constexpr (C == 1) {
        xi[0] = xb[i];
        sqi = xi[0] * xi[0];
    } else {
        const float4* xr = reinterpret_cast<const float4*>(xb + (size_t)i * C);
        #pragma unroll
        for (int c4 = 0; c4 < C / 4; c4++) {
            float4 v = xr[c4];
            xi[c4*4+0] = v.x; xi[c4*4+1] = v.y; xi[c4*4+2] = v.z; xi[c4*4+3] = v.w;
            sqi += v.x*v.x + v.y*v.y + v.z*v.z + v.w*v.w;
        }
    }

    float td[KNNK];
    int   ti[KNNK];
    #pragma unroll
    for (int k = 0; k < KNNK; k++) { td[k] = INFINITY; ti[k] = 0; }

    for (int jt = 0; jt < NPTS / PT; ++jt) {
        __syncthreads();
        {   // stage tile: thread tid loads row jt*PT + tid
            int jr = jt * PT + tid;
            float s = 0.f;
            if constexpr (C == 1) {
                float v = xb[jr];
                xs[tid] = v; s = v * v;
            } else {
                const float4* xr = reinterpret_cast<const float4*>(xb + (size_t)jr * C);
                float4* xw = reinterpret_cast<float4*>(xs + tid * C);
                #pragma unroll
                for (int c4 = 0; c4 < C / 4; c4++) {
                    float4 v = xr[c4];
                    xw[c4] = v;
                    s += v.x*v.x + v.y*v.y + v.z*v.z + v.w*v.w;
                }
            }
            sqs[tid] = s;
        }
        __syncthreads();

        for (int jj = 0; jj < PT; ++jj) {
            float dot;
            if constexpr (C == 1) {
                dot = xi[0] * xs[jj];
            } else {
                float d0 = 0, d1 = 0, d2 = 0, d3 = 0;
                const float4* xr = reinterpret_cast<const float4*>(xs + jj * C);
                #pragma unroll
                for (int c4 = 0; c4 < C / 4; c4++) {
                    float4 v = xr[c4];
                    d0 += xi[c4*4+0] * v.x; d1 += xi[c4*4+1] * v.y;
                    d2 += xi[c4*4+2] * v.z; d3 += xi[c4*4+3] * v.w;
                }
                dot = (d0 + d1) + (d2 + d3);
            }
            float d = (sqi + sqs[jj]) - 2.f * dot;
            if (d < td[KNNK - 1]) {
                td[KNNK - 1] = d;
                ti[KNNK - 1] = jt * PT + jj;
                #pragma unroll
                for (int s = KNNK - 1; s > 0; --s) {
                    if (td[s] < td[s - 1]) {
                        float tv = td[s]; td[s] = td[s - 1]; td[s - 1] = tv;
                        int   iv = ti[s]; ti[s] = ti[s - 1]; ti[s - 1] = iv;
                    }
                }
            }
        }
    }
    #pragma unroll
    for (int k = 0; k < KNNK; k++)
        idx_out[((size_t)b * NPTS + i) * KNNK + k] = ti[k];
}

// ============================================================================
// EdgeConv: out[i,t] = max_k ( relu(e_ik @ w1 + b1) @ w2 + b2 )[t]
// e_ik = [x_i, x_nbr(k) - x_i]  (2C dims). H = 64.
// Block = 256 threads = 4 groups of 64; each group processes 4 points.
// Thread t computes channel t for all 16 neighbors (16-wide accumulators);
// activations live transposed ([c][k]) in SMEM for float4 broadcast loads.
// ============================================================================
template <int C>
__host__ __device__ constexpr int ec_gsz() {
    return ((C + 3) & ~3) + 2 * C * 16 + HID * 16 + 16;
}
template <int C>
__host__ __device__ constexpr size_t ec_smem_bytes() {
    return (size_t)(2 * C * HID + HID * HID + 2 * HID + 4 * ec_gsz<C>()) * 4;
}

template <int C>
__global__ __launch_bounds__(256) void edgeconv_kernel(
    const float* __restrict__ x, const int* __restrict__ nidx,
    const float* __restrict__ w1, const float* __restrict__ b1,
    const float* __restrict__ w2, const float* __restrict__ b2,
    float* __restrict__ out) {
    constexpr int GROUPS = 4;
    constexpr int PTSG   = 4;
    constexpr int CP     = (C + 3) & ~3;
    constexpr int GSZ    = ec_gsz<C>();

    extern __shared__ __align__(16) float sm[];
    float* w1s = sm;                  // 2C * 64
    float* w2s = w1s + 2 * C * HID;   // 64 * 64
    float* b1s = w2s + HID * HID;     // 64
    float* b2s = b1s + HID;           // 64
    float* grp = b2s + HID;

    int tid = threadIdx.x;
    int g   = tid >> 6;
    int t   = tid & 63;
    float* xis = grp + g * GSZ;       // C (padded to CP)
    float* et  = xis + CP;            // [c][k] 2C x 16
    float* h1t = et + 2 * C * 16;     // [c][k] 64 x 16
    int*   nbrs = (int*)(h1t + HID * 16);  // 16

    for (int u = tid; u < 2 * C * HID; u += 256) w1s[u] = w1[u];
    for (int u = tid; u < HID * HID;   u += 256) w2s[u] = w2[u];
    if (tid < HID) { b1s[tid] = b1[tid]; b2s[tid] = b2[tid]; }
    __syncthreads();

    int base = blockIdx.x * (GROUPS * PTSG) + g * PTSG;
    int bid  = g + 1;

    for (int p = 0; p < PTSG; ++p) {
        int gi = base + p;
        int b  = gi >> 10;
        int i  = gi & (NPTS - 1);
        const float* xb = x + (size_t)b * NPTS * C;

        if (t < C)    xis[t]  = xb[(size_t)i * C + t];
        if (t < KNNK) nbrs[t] = nidx[(size_t)gi * KNNK + t];
        gbar(bid, 64);

        // gather edge features (transposed: et[c*16 + k])
        for (int u = t; u < 2 * C * KNNK; u += 64) {
            int c = u >> 4;
            int k = u & 15;
            float v;
            if (c < C) v = xis[c];
            else       v = xb[(size_t)nbrs[k] * C + (c - C)] - xis[c - C];
            et[u] = v;
        }
        gbar(bid, 64);

        // stage 1: h1[k][t] = relu(b1[t] + sum_c e[k][c] * w1[c][t])
        float acc[16];
        #pragma unroll
        for (int k = 0; k < 16; k++) acc[k] = 0.f;
        #pragma unroll 4
        for (int c = 0; c < 2 * C; c++) {
            float w = w1s[c * HID + t];
            fma16(acc, et + c * 16, w);
        }
        {
            float bb = b1s[t];
            float4* hw = reinterpret_cast<float4*>(h1t + t * 16);
            #pragma unroll
            for (int q = 0; q < 4; q++) {
                float4 hv;
                hv.x = fmaxf(acc[q*4+0] + bb, 0.f);
                hv.y = fmaxf(acc[q*4+1] + bb, 0.f);
                hv.z = fmaxf(acc[q*4+2] + bb, 0.f);
                hv.w = fmaxf(acc[q*4+3] + bb, 0.f);
                hw[q] = hv;
            }
        }
        gbar(bid, 64);

        // stage 2: h2[k][t] = b2[t] + sum_c h1[k][c] * w2[c][t]; out = max_k
        #pragma unroll
        for (int k = 0; k < 16; k++) acc[k] = 0.f;
        #pragma unroll 4
        for (int c = 0; c < HID; c++) {
            float w = w2s[c * HID + t];
            fma16(acc, h1t + c * 16, w);
        }
        {
            float b2v = b2s[t];
            float m = -INFINITY;
            #pragma unroll
            for (int k = 0; k < 16; k++) m = fmaxf(m, acc[k] + b2v);
            out[(size_t)gi * HID + t] = m;
        }
        gbar(bid, 64);
    }
}

// ============================================================================
// Final MLP: concat(x1,x2,x3) (192) -> 128 relu -> 64 relu -> 32 relu -> 2
// -> log_softmax. Block = 256 = 2 groups of 128; 16 points per group.
// All weights staged in SMEM (~140 KB dynamic).
// ============================================================================
#define MLP_GSZ (192 + 128 + 64 + 32 + 4)
__host__ __device__ constexpr size_t mlp_smem_bytes() {
    return (size_t)(192*128 + 128*64 + 64*32 + 32*2 + 128 + 64 + 32 + 4
                    + 2 * MLP_GSZ) * 4;
}

__global__ __launch_bounds__(256) void mlp_kernel(
    const float* __restrict__ x1, const float* __restrict__ x2,
    const float* __restrict__ x3,
    const float* __restrict__ mw1, const float* __restrict__ mb1,
    const float* __restrict__ mw2, const float* __restrict__ mb2,
    const float* __restrict__ mw3, const float* __restrict__ mb3,
    const float* __restrict__ mw4, const float* __restrict__ mb4,
    float* __restrict__ out) {
    extern __shared__ __align__(16) float sm[];
    float* w1s = sm;                  // 192*128
    float* w2s = w1s + 192 * 128;     // 128*64
    float* w3s = w2s + 128 * 64;      // 64*32
    float* w4s = w3s + 64 * 32;       // 32*2
    float* b1s = w4s + 64;
    float* b2s = b1s + 128;
    float* b3s = b2s + 64;
    float* b4s = b3s + 32;            // 2 (+2 pad)
    float* grp = b4s + 4;

    int tid = threadIdx.x;
    int g   = tid >> 7;
    int t   = tid & 127;
    float* feat = grp + g * MLP_GSZ;  // 192
    float* h1   = feat + 192;         // 128
    float* h2   = h1 + 128;           // 64
    float* h3   = h2 + 64;            // 32
    float* oo   = h3 + 32;            // 2

    for (int u = tid; u < 192 * 128; u += 256) w1s[u] = mw1[u];
    for (int u = tid; u < 128 * 64;  u += 256) w2s[u] = mw2[u];
    for (int u = tid; u < 64 * 32;   u += 256) w3s[u] = mw3[u];
    if (tid < 64)  w4s[tid] = mw4[tid];
    if (tid < 128) b1s[tid] = mb1[tid];
    if (tid < 64)  b2s[tid] = mb2[tid];
    if (tid < 32)  b3s[tid] = mb3[tid];
    if (tid < 2)   b4s[tid] = mb4[tid];
    __syncthreads();

    constexpr int PTSG = 16;
    int base = blockIdx.x * (2 * PTSG) + g * PTSG;
    int bid  = g + 1;

    for (int p = 0; p < PTSG; ++p) {
        int gi = base + p;
        if (t < 64) {
            feat[t]       = x1[(size_t)gi * 64 + t];
            feat[64 + t]  = x2[(size_t)gi * 64 + t];
            feat[128 + t] = x3[(size_t)gi * 64 + t];
        }
        gbar(bid, 128);

        // layer 1: 192 -> 128
        {
            float acc = 0.f;
            const float4* f4 = reinterpret_cast<const float4*>(feat);
            #pragma unroll 8
            for (int c4 = 0; c4 < 48; c4++) {
                float4 f = f4[c4];
                int c = c4 * 4;
                acc += f.x * w1s[(c+0)*128 + t];
                acc += f.y * w1s[(c+1)*128 + t];
                acc += f.z * w1s[(c+2)*128 + t];
                acc += f.w * w1s[(c+3)*128 + t];
            }
            h1[t] = fmaxf(acc + b1s[t], 0.f);
        }
        gbar(bid, 128);

        // layer 2: 128 -> 64
        if (t < 64) {
            float acc = 0.f;
            const float4* f4 = reinterpret_cast<const float4*>(h1);
            #pragma unroll 8
            for (int c4 = 0; c4 < 32; c4++) {
                float4 f = f4[c4];
                int c = c4 * 4;
                acc += f.x * w2s[(c+0)*64 + t];
                acc += f.y * w2s[(c+1)*64 + t];
                acc += f.z * w2s[(c+2)*64 + t];
                acc += f.w * w2s[(c+3)*64 + t];
            }
            h2[t] = fmaxf(acc + b2s[t], 0.f);
        }
        gbar(bid, 128);

        // layer 3: 64 -> 32
        if (t < 32) {
            float acc = 0.f;
            const float4* f4 = reinterpret_cast<const float4*>(h2);
            #pragma unroll
            for (int c4 = 0; c4 < 16; c4++) {
                float4 f = f4[c4];
                int c = c4 * 4;
                acc += f.x * w3s[(c+0)*32 + t];
                acc += f.y * w3s[(c+1)*32 + t];
                acc += f.z * w3s[(c+2)*32 + t];
                acc += f.w * w3s[(c+3)*32 + t];
            }
            h3[t] = fmaxf(acc + b3s[t], 0.f);
        }
        gbar(bid, 128);

        // layer 4: 32 -> 2
        if (t < 2) {
            float acc = 0.f;
            #pragma unroll
            for (int c = 0; c < 32; c++) acc += h3[c] * w4s[c * 2 + t];
            oo[t] = acc + b4s[t];
        }
        gbar(bid, 128);

        if (t == 0) {
            float o0 = oo[0], o1 = oo[1];
            float m = fmaxf(o0, o1);
            float l = m + logf(expf(o0 - m) + expf(o1 - m));
            out[(size_t)gi * 2 + 0] = o0 - l;
            out[(size_t)gi * 2 + 1] = o1 - l;
        }
        gbar(bid, 128);
    }
}

// ============================================================================
// Launch
// ============================================================================
extern "C" void kernel_launch(void* const* d_in, const int* in_sizes, int n_in,
                              void* d_out, int out_size) {
    const float* x    = (const float*)d_in[0];
    const float* c1w1 = (const float*)d_in[1];
    const float* c1b1 = (const float*)d_in[2];
    const float* c1w2 = (const float*)d_in[3];
    const float* c1b2 = (const float*)d_in[4];
    const float* c2w1 = (const float*)d_in[5];
    const float* c2b1 = (const float*)d_in[6];
    const float* c2w2 = (const float*)d_in[7];
    const float* c2b2 = (const float*)d_in[8];
    const float* c3w1 = (const float*)d_in[9];
    const float* c3b1 = (const float*)d_in[10];
    const float* c3w2 = (const float*)d_in[11];
    const float* c3b2 = (const float*)d_in[12];
    const float* mw1  = (const float*)d_in[13];
    const float* mb1  = (const float*)d_in[14];
    const float* mw2  = (const float*)d_in[15];
    const float* mb2  = (const float*)d_in[16];
    const float* mw3  = (const float*)d_in[17];
    const float* mb3  = (const float*)d_in[18];
    const float* mw4  = (const float*)d_in[19];
    const float* mb4  = (const float*)d_in[20];
    float* out = (float*)d_out;

    float *x1p, *x2p, *x3p;
    int* idxp;
    cudaGetSymbolAddress((void**)&x1p, g_x1);
    cudaGetSymbolAddress((void**)&x2p, g_x2);
    cudaGetSymbolAddress((void**)&x3p, g_x3);
    cudaGetSymbolAddress((void**)&idxp, g_idx);

    size_t ec1_smem = ec_smem_bytes<1>();
    size_t ec64_smem = ec_smem_bytes<64>();
    size_t mlp_smem = mlp_smem_bytes();
    cudaFuncSetAttribute(edgeconv_kernel<1>,
                         cudaFuncAttributeMaxDynamicSharedMemorySize, (int)ec1_smem);
    cudaFuncSetAttribute(edgeconv_kernel<64>,
                         cudaFuncAttributeMaxDynamicSharedMemorySize, (int)ec64_smem);
    cudaFuncSetAttribute(mlp_kernel,
                         cudaFuncAttributeMaxDynamicSharedMemorySize, (int)mlp_smem);

    const int TOTAL = BATCH * NPTS;          // 65536
    dim3 knn_grid(BATCH * (NPTS / 128));     // 512
    dim3 ec_grid(TOTAL / 16);                // 4096
    dim3 mlp_grid(TOTAL / 32);               // 2048

    knn_kernel<1><<<knn_grid, 128>>>(x, idxp);
    edgeconv_kernel<1><<<ec_grid, 256, ec1_smem>>>(x, idxp, c1w1, c1b1, c1w2, c1b2, x1p);
    knn_kernel<64><<<knn_grid, 128>>>(x1p, idxp);
    edgeconv_kernel<64><<<ec_grid, 256, ec64_smem>>>(x1p, idxp, c2w1, c2b1, c2w2, c2b2, x2p);
    knn_kernel<64><<<knn_grid, 128>>>(x2p, idxp);
    edgeconv_kernel<64><<<ec_grid, 256, ec64_smem>>>(x2p, idxp, c3w1, c3b1, c3w2, c3b2, x3p);
    mlp_kernel<<<mlp_grid, 256, mlp_smem>>>(x1p, x2p, x3p,
                                            mw1, mb1, mw2, mb2, mw3, mb3, mw4, mb4, out);
}

// round 4
// speedup vs baseline: 1.2254x; 1.2254x over previous
#include <cuda_runtime.h>
#include <math.h>

#define BATCH 64
#define NPTS  1024
#define KNNK  16
#define HID   64
#define TOTALPTS (BATCH * NPTS)

// Scratch (no allocations allowed)
__device__ float g_x1[TOTALPTS * HID];
__device__ float g_x2[TOTALPTS * HID];
__device__ float g_x3[TOTALPTS * HID];
__device__ float g_A [TOTALPTS * HID];   // x@(W1a-W1b)+b1
__device__ float g_Bm[TOTALPTS * HID];   // x@W1b
__device__ int   g_idx[TOTALPTS * KNNK];

__device__ __forceinline__ void gbar(int id, int cnt) {
    asm volatile("bar.sync %0, %1;" :: "r"(id), "r"(cnt) : "memory");
}

// ============================================================================
// kNN C=1 (cheap, keep simple per-thread scan)
// ============================================================================
__global__ __launch_bounds__(128, 4) void knn1_kernel(const float* __restrict__ x,
                                                      int* __restrict__ idx_out) {
    constexpr int PT = 128;
    __shared__ float xs[PT];

    int b   = blockIdx.x / (NPTS / PT);
    int t0  = (blockIdx.x % (NPTS / PT)) * PT;
    int tid = threadIdx.x;
    int i   = t0 + tid;
    const float* xb = x + (size_t)b * NPTS;

    float xi = xb[i];
    float sqi = xi * xi;

    float td[KNNK];
    int   ti[KNNK];
    #pragma unroll
    for (int k = 0; k < KNNK; k++) { td[k] = INFINITY; ti[k] = 0; }

    for (int jt = 0; jt < NPTS / PT; ++jt) {
        __syncthreads();
        xs[tid] = xb[jt * PT + tid];
        __syncthreads();
        for (int jj = 0; jj < PT; ++jj) {
            float xj = xs[jj];
            float d = (sqi + xj * xj) - 2.f * (xi * xj);
            if (d < td[KNNK - 1]) {
                td[KNNK - 1] = d;
                ti[KNNK - 1] = jt * PT + jj;
                #pragma unroll
                for (int s = KNNK - 1; s > 0; --s) {
                    if (td[s] < td[s - 1]) {
                        float tv = td[s]; td[s] = td[s - 1]; td[s - 1] = tv;
                        int   iv = ti[s]; ti[s] = ti[s - 1]; ti[s - 1] = iv;
                    }
                }
            }
        }
    }
    #pragma unroll
    for (int k = 0; k < KNNK; k++)
        idx_out[((size_t)b * NPTS + i) * KNNK + k] = ti[k];
}

// ============================================================================
// kNN C=64: 2 queries/thread in registers, 8:1 FMA:LDS, top-k in SMEM with
// register-cached current-max. 128 thr/block, 256 queries/block, 256 blocks.
// ============================================================================
__host__ __device__ constexpr size_t knn64_smem() {
    return (size_t)(128 * 64 + 128 + 256 * KNNK) * 4 + (size_t)(256 * KNNK) * 4;
}

__device__ __forceinline__ void topk_insert(float* td, int* ti, float d, int j) {
    int s = KNNK - 1;
    while (s > 0 && td[s - 1] > d) {
        td[s] = td[s - 1]; ti[s] = ti[s - 1]; --s;
    }
    td[s] = d; ti[s] = j;
}

__global__ __launch_bounds__(128) void knn64_kernel(const float* __restrict__ x,
                                                    int* __restrict__ idx_out) {
    extern __shared__ __align__(16) float sm[];
    float* xs   = sm;                 // 128*64
    float* sqs  = xs + 128 * 64;      // 128
    float* stdk = sqs + 128;          // 256*16
    int*   stik = (int*)(stdk + 256 * KNNK);

    int tid  = threadIdx.x;
    int b    = blockIdx.x >> 2;
    int qoff = (blockIdx.x & 3) * 256;
    const float* xb = x + (size_t)b * NPTS * 64;

    int q0 = qoff + tid, q1 = qoff + 128 + tid;
    float* td0 = stdk + tid * KNNK;
    float* td1 = stdk + (128 + tid) * KNNK;
    int*   ti0 = stik + tid * KNNK;
    int*   ti1 = stik + (128 + tid) * KNNK;

    float xi0[64], xi1[64];
    float sqi0 = 0.f, sqi1 = 0.f;
    {
        const float4* r0 = (const float4*)(xb + (size_t)q0 * 64);
        const float4* r1 = (const float4*)(xb + (size_t)q1 * 64);
        #pragma unroll
        for (int c4 = 0; c4 < 16; c4++) {
            float4 v = r0[c4];
            xi0[c4*4+0]=v.x; xi0[c4*4+1]=v.y; xi0[c4*4+2]=v.z; xi0[c4*4+3]=v.w;
            sqi0 += v.x*v.x + v.y*v.y + v.z*v.z + v.w*v.w;
            float4 w = r1[c4];
            xi1[c4*4+0]=w.x; xi1[c4*4+1]=w.y; xi1[c4*4+2]=w.z; xi1[c4*4+3]=w.w;
            sqi1 += w.x*w.x + w.y*w.y + w.z*w.z + w.w*w.w;
        }
    }
    #pragma unroll
    for (int k = 0; k < KNNK; k++) { td0[k] = INFINITY; td1[k] = INFINITY; }
    float cmax0 = INFINITY, cmax1 = INFINITY;

    for (int jt = 0; jt < 8; ++jt) {
        __syncthreads();
        {   // stage 128 candidate rows + squared norms
            int jr = jt * 128 + tid;
            const float4* r = (const float4*)(xb + (size_t)jr * 64);
            float4* w = (float4*)(xs + tid * 64);
            float s = 0.f;
            #pragma unroll
            for (int c4 = 0; c4 < 16; c4++) {
                float4 v = r[c4];
                w[c4] = v;
                s += v.x*v.x + v.y*v.y + v.z*v.z + v.w*v.w;
            }
            sqs[tid] = s;
        }
        __syncthreads();

        for (int jj = 0; jj < 128; ++jj) {
            const float4* row = (const float4*)(xs + jj * 64);
            float a0=0,a1=0,a2=0,a3=0, e0=0,e1=0,e2=0,e3=0;
            #pragma unroll
            for (int c4 = 0; c4 < 16; c4++) {
                float4 v = row[c4];
                a0 += xi0[c4*4+0]*v.x; a1 += xi0[c4*4+1]*v.y;
                a2 += xi0[c4*4+2]*v.z; a3 += xi0[c4*4+3]*v.w;
                e0 += xi1[c4*4+0]*v.x; e1 += xi1[c4*4+1]*v.y;
                e2 += xi1[c4*4+2]*v.z; e3 += xi1[c4*4+3]*v.w;
            }
            float sj = sqs[jj];
            int jg = jt * 128 + jj;
            float d0 = (sqi0 + sj) - 2.f * ((a0 + a1) + (a2 + a3));
            if (d0 < cmax0) { topk_insert(td0, ti0, d0, jg); cmax0 = td0[KNNK-1]; }
            float d1 = (sqi1 + sj) - 2.f * ((e0 + e1) + (e2 + e3));
            if (d1 < cmax1) { topk_insert(td1, ti1, d1, jg); cmax1 = td1[KNNK-1]; }
        }
    }
    #pragma unroll
    for (int k = 0; k < KNNK; k++) {
        idx_out[((size_t)b * NPTS + q0) * KNNK + k] = ti0[k];
        idx_out[((size_t)b * NPTS + q1) * KNNK + k] = ti1[k];
    }
}

// ============================================================================
// Precompute: A = x@(W1a-W1b)+b1, Bm = x@W1b.  One GEMM [128 pts x C]@[C x 128]
// per block; 256 thr as 16x16 grid, 8x8 register tiles.
// ============================================================================
template <int C>
__host__ __device__ constexpr size_t pre_smem() {
    return (size_t)(2 * C * 128 + 64) * 4;
}

template <int C>
__global__ __launch_bounds__(256) void pre_kernel(
    const float* __restrict__ x, const float* __restrict__ w1,
    const float* __restrict__ b1,
    float* __restrict__ A, float* __restrict__ Bm) {
    extern __shared__ __align__(16) float sm[];
    float* xt  = sm;             // C x 128 (k-major)
    float* wc  = xt + C * 128;   // C x 128: [ W1a-W1b | W1b ]
    float* b1s = wc + C * 128;   // 64

    int tid = threadIdx.x;
    int p0  = blockIdx.x * 128;

    for (int u = tid; u < C * 128; u += 256) {
        int c = u >> 7, j = u & 127;
        float v;
        if (j < 64) v = w1[c * 64 + j] - w1[(C + c) * 64 + j];
        else        v = w1[(C + c) * 64 + (j - 64)];
        wc[u] = v;
    }
    if constexpr (C == 1) {
        if (tid < 128) xt[tid] = x[p0 + tid];
    } else {
        int row = tid >> 1, half = tid & 1;
        const float4* r = (const float4*)(x + (size_t)(p0 + row) * C + half * 32);
        #pragma unroll
        for (int c4 = 0; c4 < 8; c4++) {
            float4 v = r[c4];
            int c = half * 32 + c4 * 4;
            xt[(c+0)*128 + row] = v.x; xt[(c+1)*128 + row] = v.y;
            xt[(c+2)*128 + row] = v.z; xt[(c+3)*128 + row] = v.w;
        }
    }
    if (tid < 64) b1s[tid] = b1[tid];
    __syncthreads();

    int tr = tid >> 4, tc = tid & 15;
    int m0 = tr * 8, n0 = tc * 8;
    float acc[8][8];
    #pragma unroll
    for (int r = 0; r < 8; r++)
        #pragma unroll
        for (int c = 0; c < 8; c++) acc[r][c] = 0.f;

    #pragma unroll 4
    for (int k = 0; k < C; k++) {
        float4 a01 = *(const float4*)(xt + k * 128 + m0);
        float4 a23 = *(const float4*)(xt + k * 128 + m0 + 4);
        float4 w01 = *(const float4*)(wc + k * 128 + n0);
        float4 w23 = *(const float4*)(wc + k * 128 + n0 + 4);
        float av[8] = {a01.x,a01.y,a01.z,a01.w,a23.x,a23.y,a23.z,a23.w};
        float wv[8] = {w01.x,w01.y,w01.z,w01.w,w23.x,w23.y,w23.z,w23.w};
        #pragma unroll
        for (int r = 0; r < 8; r++)
            #pragma unroll
            for (int c = 0; c < 8; c++) acc[r][c] += av[r] * wv[c];
    }

    if (tc < 8) {
        #pragma unroll
        for (int r = 0; r < 8; r++) {
            int p = p0 + m0 + r;
            float4 o0, o1;
            o0.x = acc[r][0] + b1s[n0+0]; o0.y = acc[r][1] + b1s[n0+1];
            o0.z = acc[r][2] + b1s[n0+2]; o0.w = acc[r][3] + b1s[n0+3];
            o1.x = acc[r][4] + b1s[n0+4]; o1.y = acc[r][5] + b1s[n0+5];
            o1.z = acc[r][6] + b1s[n0+6]; o1.w = acc[r][7] + b1s[n0+7];
            *(float4*)(A + (size_t)p * 64 + n0)     = o0;
            *(float4*)(A + (size_t)p * 64 + n0 + 4) = o1;
        }
    } else {
        int nb = n0 - 64;
        #pragma unroll
        for (int r = 0; r < 8; r++) {
            int p = p0 + m0 + r;
            float4 o0 = {acc[r][0], acc[r][1], acc[r][2], acc[r][3]};
            float4 o1 = {acc[r][4], acc[r][5], acc[r][6], acc[r][7]};
            *(float4*)(Bm + (size_t)p * 64 + nb)     = o0;
            *(float4*)(Bm + (size_t)p * 64 + nb + 4) = o1;
        }
    }
}

// ============================================================================
// Edge stage 2: h1[edge] = relu(A[i] + Bm[nbr]); out[i] = max_k (h1@W2 + b2).
// 256 thr = 4 groups x 64; group does 4 points -> M=64 edge rows, N=64,
// 8x8 thread grid with 8x8 register tiles (16:1 FMA:LDS).
// NOTE: nidx holds BATCH-LOCAL indices; convert to global with the block's
// batch base (all 16 points of a block lie in one batch).
// ============================================================================
__host__ __device__ constexpr int eg_grp() { return 4096 + 256 + 512 + 64; }
__host__ __device__ constexpr size_t edge2_smem() {
    return (size_t)(4096 + 64 + 4 * eg_grp()) * 4;
}

__global__ __launch_bounds__(256, 2) void edge2_kernel(
    const float* __restrict__ A, const float* __restrict__ Bm,
    const int* __restrict__ nidx,
    const float* __restrict__ w2, const float* __restrict__ b2,
    float* __restrict__ out) {
    extern __shared__ __align__(16) float sm[];
    float* w2s = sm;           // 64x64 k-major (row-major w2 already is)
    float* b2s = w2s + 4096;   // 64
    float* grp = b2s + 64;

    int tid = threadIdx.x, g = tid >> 6, t = tid & 63;
    float* h1t = grp + g * eg_grp();   // [c][m] 64x64
    float* ais = h1t + 4096;           // 4x64
    float* red = ais + 256;            // 8x64
    int*   nbrs = (int*)(red + 512);   // 64

    for (int u = tid; u < 4096; u += 256) w2s[u] = w2[u];
    if (tid < 64) b2s[tid] = b2[tid];
    __syncthreads();

    int gp = blockIdx.x * 16 + g * 4;
    int batch_base = (gp >> 10) << 10;   // batch start (global point id)
    int bid = g + 1;

    #pragma unroll
    for (int pt = 0; pt < 4; pt++) ais[pt * 64 + t] = A[(size_t)(gp + pt) * 64 + t];
    nbrs[t] = nidx[(size_t)gp * KNNK + t];
    gbar(bid, 64);

    {   // gather + relu -> h1t (k-major)
        int pt = t >> 4;
        int nb = batch_base + nbrs[t];   // batch-local -> global
        const float4* bv4 = (const float4*)(Bm + (size_t)nb * 64);
        const float4* av4 = (const float4*)(ais + pt * 64);
        #pragma unroll
        for (int c4 = 0; c4 < 16; c4++) {
            float4 bv = bv4[c4], av = av4[c4];
            int c = c4 * 4;
            h1t[(c+0)*64 + t] = fmaxf(av.x + bv.x, 0.f);
            h1t[(c+1)*64 + t] = fmaxf(av.y + bv.y, 0.f);
            h1t[(c+2)*64 + t] = fmaxf(av.z + bv.z, 0.f);
            h1t[(c+3)*64 + t] = fmaxf(av.w + bv.w, 0.f);
        }
    }
    gbar(bid, 64);

    int tr = t >> 3, tc = t & 7;
    int m0 = tr * 8, n0 = tc * 8;
    float acc[8][8];
    #pragma unroll
    for (int r = 0; r < 8; r++)
        #pragma unroll
        for (int c = 0; c < 8; c++) acc[r][c] = 0.f;

    #pragma unroll 4
    for (int k = 0; k < HID; k++) {
        float4 a01 = *(const float4*)(h1t + k * 64 + m0);
        float4 a23 = *(const float4*)(h1t + k * 64 + m0 + 4);
        float4 w01 = *(const float4*)(w2s + k * 64 + n0);
        float4 w23 = *(const float4*)(w2s + k * 64 + n0 + 4);
        float av[8] = {a01.x,a01.y,a01.z,a01.w,a23.x,a23.y,a23.z,a23.w};
        float wv[8] = {w01.x,w01.y,w01.z,w01.w,w23.x,w23.y,w23.z,w23.w};
        #pragma unroll
        for (int r = 0; r < 8; r++)
            #pragma unroll
            for (int c = 0; c < 8; c++) acc[r][c] += av[r] * wv[c];
    }

    // partial max over this thread's 8 rows (8 neighbors of one point-half)
    float pm[8];
    #pragma unroll
    for (int c = 0; c < 8; c++) {
        float m = acc[0][c];
        #pragma unroll
        for (int r = 1; r < 8; r++) m = fmaxf(m, acc[r][c]);
        pm[c] = m;
    }
    *(float4*)(red + tr * 64 + n0)     = make_float4(pm[0], pm[1], pm[2], pm[3]);
    *(float4*)(red + tr * 64 + n0 + 4) = make_float4(pm[4], pm[5], pm[6], pm[7]);
    gbar(bid, 64);

    #pragma unroll
    for (int pt = 0; pt < 4; pt++) {
        float v = fmaxf(red[(2*pt) * 64 + t], red[(2*pt+1) * 64 + t]) + b2s[t];
        out[(size_t)(gp + pt) * 64 + t] = v;
    }
}

// ============================================================================
// Final MLP (unchanged)
// ============================================================================
#define MLP_GSZ (192 + 128 + 64 + 32 + 4)
__host__ __device__ constexpr size_t mlp_smem_bytes() {
    return (size_t)(192*128 + 128*64 + 64*32 + 32*2 + 128 + 64 + 32 + 4
                    + 2 * MLP_GSZ) * 4;
}

__global__ __launch_bounds__(256) void mlp_kernel(
    const float* __restrict__ x1, const float* __restrict__ x2,
    const float* __restrict__ x3,
    const float* __restrict__ mw1, const float* __restrict__ mb1,
    const float* __restrict__ mw2, const float* __restrict__ mb2,
    const float* __restrict__ mw3, const float* __restrict__ mb3,
    const float* __restrict__ mw4, const float* __restrict__ mb4,
    float* __restrict__ out) {
    extern __shared__ __align__(16) float sm[];
    float* w1s = sm;
    float* w2s = w1s + 192 * 128;
    float* w3s = w2s + 128 * 64;
    float* w4s = w3s + 64 * 32;
    float* b1s = w4s + 64;
    float* b2s = b1s + 128;
    float* b3s = b2s + 64;
    float* b4s = b3s + 32;
    float* grp = b4s + 4;

    int tid = threadIdx.x;
    int g   = tid >> 7;
    int t   = tid & 127;
    float* feat = grp + g * MLP_GSZ;
    float* h1   = feat + 192;
    float* h2   = h1 + 128;
    float* h3   = h2 + 64;
    float* oo   = h3 + 32;

    for (int u = tid; u < 192 * 128; u += 256) w1s[u] = mw1[u];
    for (int u = tid; u < 128 * 64;  u += 256) w2s[u] = mw2[u];
    for (int u = tid; u < 64 * 32;   u += 256) w3s[u] = mw3[u];
    if (tid < 64)  w4s[tid] = mw4[tid];
    if (tid < 128) b1s[tid] = mb1[tid];
    if (tid < 64)  b2s[tid] = mb2[tid];
    if (tid < 32)  b3s[tid] = mb3[tid];
    if (tid < 2)   b4s[tid] = mb4[tid];
    __syncthreads();

    constexpr int PTSG = 16;
    int base = blockIdx.x * (2 * PTSG) + g * PTSG;
    int bid  = g + 1;

    for (int p = 0; p < PTSG; ++p) {
        int gi = base + p;
        if (t < 64) {
            feat[t]       = x1[(size_t)gi * 64 + t];
            feat[64 + t]  = x2[(size_t)gi * 64 + t];
            feat[128 + t] = x3[(size_t)gi * 64 + t];
        }
        gbar(bid, 128);

        {
            float acc = 0.f;
            const float4* f4 = reinterpret_cast<const float4*>(feat);
            #pragma unroll 8
            for (int c4 = 0; c4 < 48; c4++) {
                float4 f = f4[c4];
                int c = c4 * 4;
                acc += f.x * w1s[(c+0)*128 + t];
                acc += f.y * w1s[(c+1)*128 + t];
                acc += f.z * w1s[(c+2)*128 + t];
                acc += f.w * w1s[(c+3)*128 + t];
            }
            h1[t] = fmaxf(acc + b1s[t], 0.f);
        }
        gbar(bid, 128);

        if (t < 64) {
            float acc = 0.f;
            const float4* f4 = reinterpret_cast<const float4*>(h1);
            #pragma unroll 8
            for (int c4 = 0; c4 < 32; c4++) {
                float4 f = f4[c4];
                int c = c4 * 4;
                acc += f.x * w2s[(c+0)*64 + t];
                acc += f.y * w2s[(c+1)*64 + t];
                acc += f.z * w2s[(c+2)*64 + t];
                acc += f.w * w2s[(c+3)*64 + t];
            }
            h2[t] = fmaxf(acc + b2s[t], 0.f);
        }
        gbar(bid, 128);

        if (t < 32) {
            float acc = 0.f;
            const float4* f4 = reinterpret_cast<const float4*>(h2);
            #pragma unroll
            for (int c4 = 0; c4 < 16; c4++) {
                float4 f = f4[c4];
                int c = c4 * 4;
                acc += f.x * w3s[(c+0)*32 + t];
                acc += f.y * w3s[(c+1)*32 + t];
                acc += f.z * w3s[(c+2)*32 + t];
                acc += f.w * w3s[(c+3)*32 + t];
            }
            h3[t] = fmaxf(acc + b3s[t], 0.f);
        }
        gbar(bid, 128);

        if (t < 2) {
            float acc = 0.f;
            #pragma unroll
            for (int c = 0; c < 32; c++) acc += h3[c] * w4s[c * 2 + t];
            oo[t] = acc + b4s[t];
        }
        gbar(bid, 128);

        if (t == 0) {
            float o0 = oo[0], o1 = oo[1];
            float m = fmaxf(o0, o1);
            float l = m + logf(expf(o0 - m) + expf(o1 - m));
            out[(size_t)gi * 2 + 0] = o0 - l;
            out[(size_t)gi * 2 + 1] = o1 - l;
        }
        gbar(bid, 128);
    }
}

// ============================================================================
// Launch
// ============================================================================
extern "C" void kernel_launch(void* const* d_in, const int* in_sizes, int n_in,
                              void* d_out, int out_size) {
    const float* x    = (const float*)d_in[0];
    const float* c1w1 = (const float*)d_in[1];
    const float* c1b1 = (const float*)d_in[2];
    const float* c1w2 = (const float*)d_in[3];
    const float* c1b2 = (const float*)d_in[4];
    const float* c2w1 = (const float*)d_in[5];
    const float* c2b1 = (const float*)d_in[6];
    const float* c2w2 = (const float*)d_in[7];
    const float* c2b2 = (const float*)d_in[8];
    const float* c3w1 = (const float*)d_in[9];
    const float* c3b1 = (const float*)d_in[10];
    const float* c3w2 = (const float*)d_in[11];
    const float* c3b2 = (const float*)d_in[12];
    const float* mw1  = (const float*)d_in[13];
    const float* mb1  = (const float*)d_in[14];
    const float* mw2  = (const float*)d_in[15];
    const float* mb2  = (const float*)d_in[16];
    const float* mw3  = (const float*)d_in[17];
    const float* mb3  = (const float*)d_in[18];
    const float* mw4  = (const float*)d_in[19];
    const float* mb4  = (const float*)d_in[20];
    float* out = (float*)d_out;

    float *x1p, *x2p, *x3p, *Ap, *Bp;
    int* idxp;
    cudaGetSymbolAddress((void**)&x1p, g_x1);
    cudaGetSymbolAddress((void**)&x2p, g_x2);
    cudaGetSymbolAddress((void**)&x3p, g_x3);
    cudaGetSymbolAddress((void**)&Ap,  g_A);
    cudaGetSymbolAddress((void**)&Bp,  g_Bm);
    cudaGetSymbolAddress((void**)&idxp, g_idx);

    size_t kn_smem  = knn64_smem();
    size_t p64_smem = pre_smem<64>();
    size_t p1_smem  = pre_smem<1>();
    size_t e2_smem  = edge2_smem();
    size_t ml_smem  = mlp_smem_bytes();
    cudaFuncSetAttribute(knn64_kernel,
                         cudaFuncAttributeMaxDynamicSharedMemorySize, (int)kn_smem);
    cudaFuncSetAttribute(pre_kernel<64>,
                         cudaFuncAttributeMaxDynamicSharedMemorySize, (int)p64_smem);
    cudaFuncSetAttribute(edge2_kernel,
                         cudaFuncAttributeMaxDynamicSharedMemorySize, (int)e2_smem);
    cudaFuncSetAttribute(mlp_kernel,
                         cudaFuncAttributeMaxDynamicSharedMemorySize, (int)ml_smem);

    dim3 knn1_grid(BATCH * (NPTS / 128));   // 512
    dim3 knn64_grid(TOTALPTS / 256);        // 256
    dim3 pre_grid(TOTALPTS / 128);          // 512
    dim3 e2_grid(TOTALPTS / 16);            // 4096
    dim3 mlp_grid(TOTALPTS / 32);           // 2048

    // conv1
    knn1_kernel<<<knn1_grid, 128>>>(x, idxp);
    pre_kernel<1><<<pre_grid, 256, p1_smem>>>(x, c1w1, c1b1, Ap, Bp);
    edge2_kernel<<<e2_grid, 256, e2_smem>>>(Ap, Bp, idxp, c1w2, c1b2, x1p);
    // conv2
    knn64_kernel<<<knn64_grid, 128, kn_smem>>>(x1p, idxp);
    pre_kernel<64><<<pre_grid, 256, p64_smem>>>(x1p, c2w1, c2b1, Ap, Bp);
    edge2_kernel<<<e2_grid, 256, e2_smem>>>(Ap, Bp, idxp, c2w2, c2b2, x2p);
    // conv3
    knn64_kernel<<<knn64_grid, 128, kn_smem>>>(x2p, idxp);
    pre_kernel<64><<<pre_grid, 256, p64_smem>>>(x2p, c3w1, c3b1, Ap, Bp);
    edge2_kernel<<<e2_grid, 256, e2_smem>>>(Ap, Bp, idxp, c3w2, c3b2, x3p);
    // head
    mlp_kernel<<<mlp_grid, 256, ml_smem>>>(x1p, x2p, x3p,
                                           mw1, mb1, mw2, mb2, mw3, mb3, mw4, mb4, out);
}

// round 5
// speedup vs baseline: 1.5368x; 1.2541x over previous
#include <cuda_runtime.h>
#include <math.h>

#define BATCH 64
#define NPTS  1024
#define KNNK  16
#define HID   64
#define TOTALPTS (BATCH * NPTS)

// Scratch (no allocations allowed)
__device__ float g_x1[TOTALPTS * HID];
__device__ float g_x2[TOTALPTS * HID];
__device__ float g_x3[TOTALPTS * HID];
__device__ float g_A [TOTALPTS * HID];   // x@(W1a-W1b)+b1
__device__ float g_Bm[TOTALPTS * HID];   // x@W1b
__device__ int   g_idx[TOTALPTS * KNNK];

__device__ __forceinline__ void gbar(int id, int cnt) {
    asm volatile("bar.sync %0, %1;" :: "r"(id), "r"(cnt) : "memory");
}

// ============================================================================
// kNN C=1 (cheap, keep simple per-thread scan)
// ============================================================================
__global__ __launch_bounds__(128, 4) void knn1_kernel(const float* __restrict__ x,
                                                      int* __restrict__ idx_out) {
    constexpr int PT = 128;
    __shared__ float xs[PT];

    int b   = blockIdx.x / (NPTS / PT);
    int t0  = (blockIdx.x % (NPTS / PT)) * PT;
    int tid = threadIdx.x;
    int i   = t0 + tid;
    const float* xb = x + (size_t)b * NPTS;

    float xi = xb[i];
    float sqi = xi * xi;

    float td[KNNK];
    int   ti[KNNK];
    #pragma unroll
    for (int k = 0; k < KNNK; k++) { td[k] = INFINITY; ti[k] = 0; }

    for (int jt = 0; jt < NPTS / PT; ++jt) {
        __syncthreads();
        xs[tid] = xb[jt * PT + tid];
        __syncthreads();
        for (int jj = 0; jj < PT; ++jj) {
            float xj = xs[jj];
            float d = (sqi + xj * xj) - 2.f * (xi * xj);
            if (d < td[KNNK - 1]) {
                td[KNNK - 1] = d;
                ti[KNNK - 1] = jt * PT + jj;
                #pragma unroll
                for (int s = KNNK - 1; s > 0; --s) {
                    if (td[s] < td[s - 1]) {
                        float tv = td[s]; td[s] = td[s - 1]; td[s - 1] = tv;
                        int   iv = ti[s]; ti[s] = ti[s - 1]; ti[s - 1] = iv;
                    }
                }
            }
        }
    }
    #pragma unroll
    for (int k = 0; k < KNNK; k++)
        idx_out[((size_t)b * NPTS + i) * KNNK + k] = ti[k];
}

// ============================================================================
// kNN C=64 v2: 256 thr/block, 1 query/thread (low regs -> 16 warps/SM),
// candidate tiles of 128 rows staged in SMEM, top-k in SMEM stride 17
// (conflict-free). 256 queries/block, 256 blocks.
// ============================================================================
#define TKS 17   // padded top-k stride
__host__ __device__ constexpr size_t knn64_smem() {
    return (size_t)(128 * 64 + 128 + 256 * TKS) * 4 + (size_t)(256 * TKS) * 4;
}

__device__ __forceinline__ void topk_insert(float* td, int* ti, float d, int j) {
    int s = KNNK - 1;
    while (s > 0 && td[s - 1] > d) {
        td[s] = td[s - 1]; ti[s] = ti[s - 1]; --s;
    }
    td[s] = d; ti[s] = j;
}

__global__ __launch_bounds__(256, 2) void knn64_kernel(const float* __restrict__ x,
                                                       int* __restrict__ idx_out) {
    extern __shared__ __align__(16) float sm[];
    float* xs   = sm;                 // 128*64
    float* sqs  = xs + 128 * 64;      // 128
    float* stdk = sqs + 128;          // 256*TKS
    int*   stik = (int*)(stdk + 256 * TKS);

    int tid  = threadIdx.x;
    int b    = blockIdx.x >> 2;
    int qoff = (blockIdx.x & 3) * 256;
    const float* xb = x + (size_t)b * NPTS * 64;

    int q = qoff + tid;
    float* td = stdk + tid * TKS;
    int*   ti = stik + tid * TKS;

    float xi[64];
    float sqi = 0.f;
    {
        const float4* r = (const float4*)(xb + (size_t)q * 64);
        #pragma unroll
        for (int c4 = 0; c4 < 16; c4++) {
            float4 v = r[c4];
            xi[c4*4+0]=v.x; xi[c4*4+1]=v.y; xi[c4*4+2]=v.z; xi[c4*4+3]=v.w;
            sqi += v.x*v.x + v.y*v.y + v.z*v.z + v.w*v.w;
        }
    }
    #pragma unroll
    for (int k = 0; k < KNNK; k++) td[k] = INFINITY;
    float cmax = INFINITY;

    for (int jt = 0; jt < 8; ++jt) {
        __syncthreads();
        {   // stage 128 candidate rows: 256 thr, each loads half a row
            int row  = tid >> 1, half = tid & 1;
            int jr   = jt * 128 + row;
            const float4* r = (const float4*)(xb + (size_t)jr * 64 + half * 32);
            float4* w = (float4*)(xs + row * 64 + half * 32);
            float s = 0.f;
            #pragma unroll
            for (int c4 = 0; c4 < 8; c4++) {
                float4 v = r[c4];
                w[c4] = v;
                s += v.x*v.x + v.y*v.y + v.z*v.z + v.w*v.w;
            }
            // two halves contribute: use atomic-free split — store partial then add
            if (half == 0) sqs[row] = s;
        }
        __syncthreads();
        {   // add second-half norms
            int row = tid >> 1, half = tid & 1;
            if (half == 1) {
                float s = 0.f;
                const float4* w = (const float4*)(xs + row * 64 + 32);
                #pragma unroll
                for (int c4 = 0; c4 < 8; c4++) {
                    float4 v = w[c4];
                    s += v.x*v.x + v.y*v.y + v.z*v.z + v.w*v.w;
                }
                sqs[row] += s;
            }
        }
        __syncthreads();

        for (int jj = 0; jj < 128; ++jj) {
            const float4* row = (const float4*)(xs + jj * 64);
            float a0=0,a1=0,a2=0,a3=0;
            #pragma unroll
            for (int c4 = 0; c4 < 16; c4++) {
                float4 v = row[c4];
                a0 += xi[c4*4+0]*v.x; a1 += xi[c4*4+1]*v.y;
                a2 += xi[c4*4+2]*v.z; a3 += xi[c4*4+3]*v.w;
            }
            float d = (sqi + sqs[jj]) - 2.f * ((a0 + a1) + (a2 + a3));
            if (d < cmax) {
                topk_insert(td, ti, d, jt * 128 + jj);
                cmax = td[KNNK - 1];
            }
        }
    }
    #pragma unroll
    for (int k = 0; k < KNNK; k++)
        idx_out[((size_t)b * NPTS + q) * KNNK + k] = ti[k];
}

// ============================================================================
// Precompute: A = x@(W1a-W1b)+b1, Bm = x@W1b.  One GEMM [128 pts x C]@[C x 128]
// per block; 256 thr as 16x16 grid, 8x8 register tiles.
// ============================================================================
template <int C>
__host__ __device__ constexpr size_t pre_smem() {
    return (size_t)(2 * C * 128 + 64) * 4;
}

template <int C>
__global__ __launch_bounds__(256) void pre_kernel(
    const float* __restrict__ x, const float* __restrict__ w1,
    const float* __restrict__ b1,
    float* __restrict__ A, float* __restrict__ Bm) {
    extern __shared__ __align__(16) float sm[];
    float* xt  = sm;             // C x 128 (k-major)
    float* wc  = xt + C * 128;   // C x 128: [ W1a-W1b | W1b ]
    float* b1s = wc + C * 128;   // 64

    int tid = threadIdx.x;
    int p0  = blockIdx.x * 128;

    for (int u = tid; u < C * 128; u += 256) {
        int c = u >> 7, j = u & 127;
        float v;
        if (j < 64) v = w1[c * 64 + j] - w1[(C + c) * 64 + j];
        else        v = w1[(C + c) * 64 + (j - 64)];
        wc[u] = v;
    }
    if constexpr (C == 1) {
        if (tid < 128) xt[tid] = x[p0 + tid];
    } else {
        int row = tid >> 1, half = tid & 1;
        const float4* r = (const float4*)(x + (size_t)(p0 + row) * C + half * 32);
        #pragma unroll
        for (int c4 = 0; c4 < 8; c4++) {
            float4 v = r[c4];
            int c = half * 32 + c4 * 4;
            xt[(c+0)*128 + row] = v.x; xt[(c+1)*128 + row] = v.y;
            xt[(c+2)*128 + row] = v.z; xt[(c+3)*128 + row] = v.w;
        }
    }
    if (tid < 64) b1s[tid] = b1[tid];
    __syncthreads();

    int tr = tid >> 4, tc = tid & 15;
    int m0 = tr * 8, n0 = tc * 8;
    float acc[8][8];
    #pragma unroll
    for (int r = 0; r < 8; r++)
        #pragma unroll
        for (int c = 0; c < 8; c++) acc[r][c] = 0.f;

    #pragma unroll 4
    for (int k = 0; k < C; k++) {
        float4 a01 = *(const float4*)(xt + k * 128 + m0);
        float4 a23 = *(const float4*)(xt + k * 128 + m0 + 4);
        float4 w01 = *(const float4*)(wc + k * 128 + n0);
        float4 w23 = *(const float4*)(wc + k * 128 + n0 + 4);
        float av[8] = {a01.x,a01.y,a01.z,a01.w,a23.x,a23.y,a23.z,a23.w};
        float wv[8] = {w01.x,w01.y,w01.z,w01.w,w23.x,w23.y,w23.z,w23.w};
        #pragma unroll
        for (int r = 0; r < 8; r++)
            #pragma unroll
            for (int c = 0; c < 8; c++) acc[r][c] += av[r] * wv[c];
    }

    if (tc < 8) {
        #pragma unroll
        for (int r = 0; r < 8; r++) {
            int p = p0 + m0 + r;
            float4 o0, o1;
            o0.x = acc[r][0] + b1s[n0+0]; o0.y = acc[r][1] + b1s[n0+1];
            o0.z = acc[r][2] + b1s[n0+2]; o0.w = acc[r][3] + b1s[n0+3];
            o1.x = acc[r][4] + b1s[n0+4]; o1.y = acc[r][5] + b1s[n0+5];
            o1.z = acc[r][6] + b1s[n0+6]; o1.w = acc[r][7] + b1s[n0+7];
            *(float4*)(A + (size_t)p * 64 + n0)     = o0;
            *(float4*)(A + (size_t)p * 64 + n0 + 4) = o1;
        }
    } else {
        int nb = n0 - 64;
        #pragma unroll
        for (int r = 0; r < 8; r++) {
            int p = p0 + m0 + r;
            float4 o0 = {acc[r][0], acc[r][1], acc[r][2], acc[r][3]};
            float4 o1 = {acc[r][4], acc[r][5], acc[r][6], acc[r][7]};
            *(float4*)(Bm + (size_t)p * 64 + nb)     = o0;
            *(float4*)(Bm + (size_t)p * 64 + nb + 4) = o1;
        }
    }
}

// ============================================================================
// Edge stage 2: h1[edge] = relu(A[i] + Bm[nbr]); out[i] = max_k (h1@W2 + b2).
// 256 thr = 4 groups x 64; group does 4 points -> M=64 edge rows, N=64,
// 8x8 thread grid with 8x8 register tiles (16:1 FMA:LDS).
// nidx holds BATCH-LOCAL indices; convert with the block's batch base.
// ============================================================================
__host__ __device__ constexpr int eg_grp() { return 4096 + 256 + 512 + 64; }
__host__ __device__ constexpr size_t edge2_smem() {
    return (size_t)(4096 + 64 + 4 * eg_grp()) * 4;
}

__global__ __launch_bounds__(256, 2) void edge2_kernel(
    const float* __restrict__ A, const float* __restrict__ Bm,
    const int* __restrict__ nidx,
    const float* __restrict__ w2, const float* __restrict__ b2,
    float* __restrict__ out) {
    extern __shared__ __align__(16) float sm[];
    float* w2s = sm;           // 64x64 k-major (row-major w2 already is)
    float* b2s = w2s + 4096;   // 64
    float* grp = b2s + 64;

    int tid = threadIdx.x, g = tid >> 6, t = tid & 63;
    float* h1t = grp + g * eg_grp();   // [c][m] 64x64
    float* ais = h1t + 4096;           // 4x64
    float* red = ais + 256;            // 8x64
    int*   nbrs = (int*)(red + 512);   // 64

    for (int u = tid; u < 4096; u += 256) w2s[u] = w2[u];
    if (tid < 64) b2s[tid] = b2[tid];
    __syncthreads();

    int gp = blockIdx.x * 16 + g * 4;
    int batch_base = (gp >> 10) << 10;   // batch start (global point id)
    int bid = g + 1;

    #pragma unroll
    for (int pt = 0; pt < 4; pt++) ais[pt * 64 + t] = A[(size_t)(gp + pt) * 64 + t];
    nbrs[t] = nidx[(size_t)gp * KNNK + t];
    gbar(bid, 64);

    {   // gather + relu -> h1t (k-major)
        int pt = t >> 4;
        int nb = batch_base + nbrs[t];   // batch-local -> global
        const float4* bv4 = (const float4*)(Bm + (size_t)nb * 64);
        const float4* av4 = (const float4*)(ais + pt * 64);
        #pragma unroll
        for (int c4 = 0; c4 < 16; c4++) {
            float4 bv = bv4[c4], av = av4[c4];
            int c = c4 * 4;
            h1t[(c+0)*64 + t] = fmaxf(av.x + bv.x, 0.f);
            h1t[(c+1)*64 + t] = fmaxf(av.y + bv.y, 0.f);
            h1t[(c+2)*64 + t] = fmaxf(av.z + bv.z, 0.f);
            h1t[(c+3)*64 + t] = fmaxf(av.w + bv.w, 0.f);
        }
    }
    gbar(bid, 64);

    int tr = t >> 3, tc = t & 7;
    int m0 = tr * 8, n0 = tc * 8;
    float acc[8][8];
    #pragma unroll
    for (int r = 0; r < 8; r++)
        #pragma unroll
        for (int c = 0; c < 8; c++) acc[r][c] = 0.f;

    #pragma unroll 4
    for (int k = 0; k < HID; k++) {
        float4 a01 = *(const float4*)(h1t + k * 64 + m0);
        float4 a23 = *(const float4*)(h1t + k * 64 + m0 + 4);
        float4 w01 = *(const float4*)(w2s + k * 64 + n0);
        float4 w23 = *(const float4*)(w2s + k * 64 + n0 + 4);
        float av[8] = {a01.x,a01.y,a01.z,a01.w,a23.x,a23.y,a23.z,a23.w};
        float wv[8] = {w01.x,w01.y,w01.z,w01.w,w23.x,w23.y,w23.z,w23.w};
        #pragma unroll
        for (int r = 0; r < 8; r++)
            #pragma unroll
            for (int c = 0; c < 8; c++) acc[r][c] += av[r] * wv[c];
    }

    // partial max over this thread's 8 rows (8 neighbors of one point-half)
    float pm[8];
    #pragma unroll
    for (int c = 0; c < 8; c++) {
        float m = acc[0][c];
        #pragma unroll
        for (int r = 1; r < 8; r++) m = fmaxf(m, acc[r][c]);
        pm[c] = m;
    }
    *(float4*)(red + tr * 64 + n0)     = make_float4(pm[0], pm[1], pm[2], pm[3]);
    *(float4*)(red + tr * 64 + n0 + 4) = make_float4(pm[4], pm[5], pm[6], pm[7]);
    gbar(bid, 64);

    #pragma unroll
    for (int pt = 0; pt < 4; pt++) {
        float v = fmaxf(red[(2*pt) * 64 + t], red[(2*pt+1) * 64 + t]) + b2s[t];
        out[(size_t)(gp + pt) * 64 + t] = v;
    }
}

// ============================================================================
// Final MLP: 4-way split accumulators for ILP (reassociation, fp error ~1e-7)
// ============================================================================
#define MLP_GSZ (192 + 128 + 64 + 32 + 4)
__host__ __device__ constexpr size_t mlp_smem_bytes() {
    return (size_t)(192*128 + 128*64 + 64*32 + 32*2 + 128 + 64 + 32 + 4
                    + 2 * MLP_GSZ) * 4;
}

__global__ __launch_bounds__(256) void mlp_kernel(
    const float* __restrict__ x1, const float* __restrict__ x2,
    const float* __restrict__ x3,
    const float* __restrict__ mw1, const float* __restrict__ mb1,
    const float* __restrict__ mw2, const float* __restrict__ mb2,
    const float* __restrict__ mw3, const float* __restrict__ mb3,
    const float* __restrict__ mw4, const float* __restrict__ mb4,
    float* __restrict__ out) {
    extern __shared__ __align__(16) float sm[];
    float* w1s = sm;
    float* w2s = w1s + 192 * 128;
    float* w3s = w2s + 128 * 64;
    float* w4s = w3s + 64 * 32;
    float* b1s = w4s + 64;
    float* b2s = b1s + 128;
    float* b3s = b2s + 64;
    float* b4s = b3s + 32;
    float* grp = b4s + 4;

    int tid = threadIdx.x;
    int g   = tid >> 7;
    int t   = tid & 127;
    float* feat = grp + g * MLP_GSZ;
    float* h1   = feat + 192;
    float* h2   = h1 + 128;
    float* h3   = h2 + 64;
    float* oo   = h3 + 32;

    for (int u = tid; u < 192 * 128; u += 256) w1s[u] = mw1[u];
    for (int u = tid; u < 128 * 64;  u += 256) w2s[u] = mw2[u];
    for (int u = tid; u < 64 * 32;   u += 256) w3s[u] = mw3[u];
    if (tid < 64)  w4s[tid] = mw4[tid];
    if (tid < 128) b1s[tid] = mb1[tid];
    if (tid < 64)  b2s[tid] = mb2[tid];
    if (tid < 32)  b3s[tid] = mb3[tid];
    if (tid < 2)   b4s[tid] = mb4[tid];
    __syncthreads();

    constexpr int PTSG = 16;
    int base = blockIdx.x * (2 * PTSG) + g * PTSG;
    int bid  = g + 1;

    for (int p = 0; p < PTSG; ++p) {
        int gi = base + p;
        if (t < 64) {
            feat[t]       = x1[(size_t)gi * 64 + t];
            feat[64 + t]  = x2[(size_t)gi * 64 + t];
            feat[128 + t] = x3[(size_t)gi * 64 + t];
        }
        gbar(bid, 128);

        {
            float a0=0,a1=0,a2=0,a3=0;
            const float4* f4 = reinterpret_cast<const float4*>(feat);
            #pragma unroll 8
            for (int c4 = 0; c4 < 48; c4++) {
                float4 f = f4[c4];
                int c = c4 * 4;
                a0 += f.x * w1s[(c+0)*128 + t];
                a1 += f.y * w1s[(c+1)*128 + t];
                a2 += f.z * w1s[(c+2)*128 + t];
                a3 += f.w * w1s[(c+3)*128 + t];
            }
            h1[t] = fmaxf(((a0+a1)+(a2+a3)) + b1s[t], 0.f);
        }
        gbar(bid, 128);

        if (t < 64) {
            float a0=0,a1=0,a2=0,a3=0;
            const float4* f4 = reinterpret_cast<const float4*>(h1);
            #pragma unroll 8
            for (int c4 = 0; c4 < 32; c4++) {
                float4 f = f4[c4];
                int c = c4 * 4;
                a0 += f.x * w2s[(c+0)*64 + t];
                a1 += f.y * w2s[(c+1)*64 + t];
                a2 += f.z * w2s[(c+2)*64 + t];
                a3 += f.w * w2s[(c+3)*64 + t];
            }
            h2[t] = fmaxf(((a0+a1)+(a2+a3)) + b2s[t], 0.f);
        }
        gbar(bid, 128);

        if (t < 32) {
            float a0=0,a1=0,a2=0,a3=0;
            const float4* f4 = reinterpret_cast<const float4*>(h2);
            #pragma unroll
            for (int c4 = 0; c4 < 16; c4++) {
                float4 f = f4[c4];
                int c = c4 * 4;
                a0 += f.x * w3s[(c+0)*32 + t];
                a1 += f.y * w3s[(c+1)*32 + t];
                a2 += f.z * w3s[(c+2)*32 + t];
                a3 += f.w * w3s[(c+3)*32 + t];
            }
            h3[t] = fmaxf(((a0+a1)+(a2+a3)) + b3s[t], 0.f);
        }
        gbar(bid, 128);

        if (t < 2) {
            float acc = 0.f;
            #pragma unroll
            for (int c = 0; c < 32; c++) acc += h3[c] * w4s[c * 2 + t];
            oo[t] = acc + b4s[t];
        }
        gbar(bid, 128);

        if (t == 0) {
            float o0 = oo[0], o1 = oo[1];
            float m = fmaxf(o0, o1);
            float l = m + logf(expf(o0 - m) + expf(o1 - m));
            out[(size_t)gi * 2 + 0] = o0 - l;
            out[(size_t)gi * 2 + 1] = o1 - l;
        }
        gbar(bid, 128);
    }
}

// ============================================================================
// Launch
// ============================================================================
extern "C" void kernel_launch(void* const* d_in, const int* in_sizes, int n_in,
                              void* d_out, int out_size) {
    const float* x    = (const float*)d_in[0];
    const float* c1w1 = (const float*)d_in[1];
    const float* c1b1 = (const float*)d_in[2];
    const float* c1w2 = (const float*)d_in[3];
    const float* c1b2 = (const float*)d_in[4];
    const float* c2w1 = (const float*)d_in[5];
    const float* c2b1 = (const float*)d_in[6];
    const float* c2w2 = (const float*)d_in[7];
    const float* c2b2 = (const float*)d_in[8];
    const float* c3w1 = (const float*)d_in[9];
    const float* c3b1 = (const float*)d_in[10];
    const float* c3w2 = (const float*)d_in[11];
    const float* c3b2 = (const float*)d_in[12];
    const float* mw1  = (const float*)d_in[13];
    const float* mb1  = (const float*)d_in[14];
    const float* mw2  = (const float*)d_in[15];
    const float* mb2  = (const float*)d_in[16];
    const float* mw3  = (const float*)d_in[17];
    const float* mb3  = (const float*)d_in[18];
    const float* mw4  = (const float*)d_in[19];
    const float* mb4  = (const float*)d_in[20];
    float* out = (float*)d_out;

    float *x1p, *x2p, *x3p, *Ap, *Bp;
    int* idxp;
    cudaGetSymbolAddress((void**)&x1p, g_x1);
    cudaGetSymbolAddress((void**)&x2p, g_x2);
    cudaGetSymbolAddress((void**)&x3p, g_x3);
    cudaGetSymbolAddress((void**)&Ap,  g_A);
    cudaGetSymbolAddress((void**)&Bp,  g_Bm);
    cudaGetSymbolAddress((void**)&idxp, g_idx);

    size_t kn_smem  = knn64_smem();
    size_t p64_smem = pre_smem<64>();
    size_t p1_smem  = pre_smem<1>();
    size_t e2_smem  = edge2_smem();
    size_t ml_smem  = mlp_smem_bytes();
    cudaFuncSetAttribute(knn64_kernel,
                         cudaFuncAttributeMaxDynamicSharedMemorySize, (int)kn_smem);
    cudaFuncSetAttribute(pre_kernel<64>,
                         cudaFuncAttributeMaxDynamicSharedMemorySize, (int)p64_smem);
    cudaFuncSetAttribute(edge2_kernel,
                         cudaFuncAttributeMaxDynamicSharedMemorySize, (int)e2_smem);
    cudaFuncSetAttribute(mlp_kernel,
                         cudaFuncAttributeMaxDynamicSharedMemorySize, (int)ml_smem);

    dim3 knn1_grid(BATCH * (NPTS / 128));   // 512
    dim3 knn64_grid(TOTALPTS / 256);        // 256
    dim3 pre_grid(TOTALPTS / 128);          // 512
    dim3 e2_grid(TOTALPTS / 16);            // 4096
    dim3 mlp_grid(TOTALPTS / 32);           // 2048

    // conv1
    knn1_kernel<<<knn1_grid, 128>>>(x, idxp);
    pre_kernel<1><<<pre_grid, 256, p1_smem>>>(x, c1w1, c1b1, Ap, Bp);
    edge2_kernel<<<e2_grid, 256, e2_smem>>>(Ap, Bp, idxp, c1w2, c1b2, x1p);
    // conv2
    knn64_kernel<<<knn64_grid, 256, kn_smem>>>(x1p, idxp);
    pre_kernel<64><<<pre_grid, 256, p64_smem>>>(x1p, c2w1, c2b1, Ap, Bp);
    edge2_kernel<<<e2_grid, 256, e2_smem>>>(Ap, Bp, idxp, c2w2, c2b2, x2p);
    // conv3
    knn64_kernel<<<knn64_grid, 256, kn_smem>>>(x2p, idxp);
    pre_kernel<64><<<pre_grid, 256, p64_smem>>>(x2p, c3w1, c3b1, Ap, Bp);
    edge2_kernel<<<e2_grid, 256, e2_smem>>>(Ap, Bp, idxp, c3w2, c3b2, x3p);
    // head
    mlp_kernel<<<mlp_grid, 256, ml_smem>>>(x1p, x2p, x3p,
                                           mw1, mb1, mw2, mb2, mw3, mb3, mw4, mb4, out);
}